// round 17
// baseline (speedup 1.0000x reference)
#include <cuda_runtime.h>
#include <cuda_fp16.h>
#include <math.h>
#include <stdint.h>
#include <mma.h>
using namespace nvcuda;

#define Bn 128
#define Tn 512
#define In 128
#define Hn 1024
#define Gn 4096
#define KHn 1024
#define KCAT 1152
#define BHn (Bn*Hn)

// Stage (BK=128): A[64][136] + B[64][136] half = 34816 B; ring of 4.
#define PITCH 136
#define OFF_Ah 0
#define OFF_Bh 8704             // 64*136 halves
#define STAGE_BYTES 34816
#define SMEM_BYTES (4*STAGE_BYTES)   // 139264 B

// ---------------------------------------------------------------------------
// Static device scratch — referenced ONLY from device code (GB300/ATS trap:
// host-passing a __device__ symbol silently uses the host shadow address)
// ---------------------------------------------------------------------------
__device__ __half g_Wenc[(size_t)Gn*KCAT];     // fp16, [n][k]
__device__ __half g_Wdec[(size_t)Gn*KCAT];
__device__ __half g_Wsum16[(size_t)Gn*KHn];
__device__ __half g_linw16[(size_t)In*Hn];     // lin_W fp16, [n][k]
__device__ __half g_xH[(size_t)Tn*Bn*In];      // [t][m][k] fp16
__device__ __half g_hH[2][BHn];                // [m][h] fp16
__device__ float  g_c[BHn];
__device__ __half g_dech16[(size_t)Tn*BHn];    // [s][b][h] fp16
__device__ float  g_benc[Gn], g_bdec[Gn], g_b2dec[Gn];
__device__ unsigned g_arr2[64];                // 2 counters, 128B apart

__device__ __forceinline__ float sigf(float x){ return 1.f/(1.f+__expf(-x)); }
__device__ __forceinline__ void cp16(uint32_t dst, const void* src){
    asm volatile("cp.async.cg.shared.global [%0],[%1],16;\n" :: "r"(dst), "l"(src));
}

// ---------------------------------------------------------------------------
// Prep kernels (elementwise)
// ---------------------------------------------------------------------------
__global__ void zero_state_kernel(){
    int i = blockIdx.x*blockDim.x + threadIdx.x;
    if (i < 64) g_arr2[i] = 0u;
    if (i < BHn){
        g_hH[0][i] = __float2half(0.f);
        g_c[i] = 0.f;
    }
}

// which: 0 enc, 1 dec. dst[n][k]; packed col n -> unit n>>2, gate n&3
__global__ void pack_w_kernel(const float* __restrict__ Whh,
                              const float* __restrict__ Wih,
                              int which){
    size_t idx = (size_t)blockIdx.x*256 + threadIdx.x;
    if (idx >= (size_t)Gn*KCAT) return;
    int n = (int)(idx / KCAT), k = (int)(idx - (size_t)n*KCAT);
    int srcrow = (n & 3)*Hn + (n >> 2);
    float v = (k < KHn) ? Whh[(size_t)srcrow*KHn + k] : Wih[(size_t)srcrow*In + (k - KHn)];
    ((which == 0) ? g_Wenc : g_Wdec)[idx] = __float2half(v);
}

__global__ void pack_x_kernel(const float* __restrict__ x){
    size_t idx = (size_t)blockIdx.x*256 + threadIdx.x;
    if (idx >= (size_t)Tn*Bn*In) return;
    int k = (int)(idx & (In - 1));
    int m = (int)((idx >> 7) & (Bn - 1));
    int t = (int)(idx >> 14);
    g_xH[idx] = __float2half(x[((size_t)m*Tn + t)*In + k]);
}

__global__ void pack_linw_kernel(const float* __restrict__ linW){
    int i = blockIdx.x*256 + threadIdx.x;
    if (i < In*Hn) g_linw16[i] = __float2half(linW[i]);   // already [n][k]
}

// Fused: Wsum = dec_Whh + dec_Wih @ lin_W, written DIRECTLY as packed fp16.
// blockIdx.x = source row n = gate*H + unit; packed row = (unit<<2)|gate.
__global__ __launch_bounds__(256) void build_wsum_kernel(
    const float* __restrict__ Whh, const float* __restrict__ Wih,
    const float* __restrict__ linW){
    const int n = blockIdx.x;
    const int npk = ((n & (Hn - 1)) << 2) | (n >> 10);
    __shared__ float wr[In];
    if (threadIdx.x < In) wr[threadIdx.x] = Wih[n*In + threadIdx.x];
    __syncthreads();
    #pragma unroll
    for (int c = 0; c < 4; c++){
        int k = threadIdx.x + 256*c;
        float s = 0.0f;
        #pragma unroll 8
        for (int j = 0; j < In; j++) s = fmaf(wr[j], linW[j*Hn + k], s);
        g_Wsum16[(size_t)npk*KHn + k] = __float2half(Whh[(size_t)n*KHn + k] + s);
    }
}

__global__ void build_bias_kernel(const float* __restrict__ ebih, const float* __restrict__ ebhh,
                                  const float* __restrict__ dbih, const float* __restrict__ dbhh,
                                  const float* __restrict__ dWih, const float* __restrict__ linb){
    int n = blockIdx.x*blockDim.x + threadIdx.x;
    if (n < Gn){
        g_benc[n] = ebih[n] + ebhh[n];
        float bd = dbih[n] + dbhh[n];
        g_bdec[n] = bd;
        float s = 0.0f;
        #pragma unroll 8
        for (int j = 0; j < In; j++) s = fmaf(dWih[n*In + j], linb[j], s);
        g_b2dec[n] = bd + s;
    }
}

// ---------------------------------------------------------------------------
// Persistent recurrence: 1-term FP16 wmma, BK=128, 4-deep ring.
// x-stage-first K order (stage 0 = x columns, h-independent -> prefetchable
// across the barrier). Split barrier: 2 independent 64-CTA groups by mt.
// 128 CTAs x 256 threads; block tile 64(M) x 64(N); warp tile 16x32.
// D f32[64][68] aliases ring slot 3.
// ---------------------------------------------------------------------------
__global__ __launch_bounds__(256, 1) void lstm_persist_kernel(
    const int* __restrict__ lengths, const int* __restrict__ tf_mask,
    float* __restrict__ enc_out){
    extern __shared__ __align__(16) char DS[];
    __half* RINGh = (__half*)DS;
    float*  Dsm   = (float*)(DS + 3*STAGE_BYTES);    // alias of slot 3
    const uint32_t ring_base = (uint32_t)__cvta_generic_to_shared(DS);
    const int tid = threadIdx.x, wid = tid >> 5;
    const int wm = wid & 3, wn = wid >> 2;           // warp rows wm*16, cols wn*32
    const int mt = blockIdx.x >> 6, nt = blockIdx.x & 63;
    volatile unsigned* ctr = &g_arr2[mt*32];

    // fixed per-thread epilogue coordinates
    const int ml = tid >> 2;
    const int m  = mt*64 + ml;
    const int ubase = nt*16 + (tid & 3)*4;           // 4 consecutive units
    const size_t idx0 = (size_t)m*Hn + ubase;

    // stage -> k0 map: KCAT steps put the x columns first
    // s=0 -> 1024 (x), s>=1 -> (s-1)*128 ; KHn steps: s*128

    // prologue prefetch for step 0 (enc): W stages 0..2 + A stage 0 (x, t=0)
    #pragma unroll
    for (int s = 0; s < 3; s++){
        const int k0 = (s == 0) ? KHn : (s - 1) << 7;
        const uint32_t sb = ring_base + (uint32_t)s*STAGE_BYTES;
        #pragma unroll
        for (int i = 0; i < 4; i++){
            int c = tid + (i << 8);
            int r = c >> 4, q = c & 15;
            cp16(sb + (uint32_t)((OFF_Bh + r*PITCH + (q << 3))*2),
                 g_Wenc + (size_t)(nt*64 + r)*KCAT + k0 + (q << 3));
        }
    }
    #pragma unroll
    for (int i = 0; i < 4; i++){
        int c = tid + (i << 8);
        int r = c >> 4, q = c & 15;
        cp16(ring_base + (uint32_t)((OFF_Ah + r*PITCH + (q << 3))*2),
             g_xH + (size_t)(mt*64 + r)*In + (q << 3));    // t=0
    }

    for (int it = 0; it < 2*Tn; it++){
        const int mode = it >= Tn;
        const int step = mode ? it - Tn : it;
        const int pin = it & 1, pout = pin ^ 1;

        // prefetch cell state early (CTA-private)
        const float4 cold4 = *(const float4*)&g_c[idx0];

        const __half* W; const float* bias; int K, ts;
        if (!mode){ W = g_Wenc; bias = g_benc; K = KCAT; ts = step; }
        else {
            int teach;
            if (step == 0){ teach = 1; ts = Tn - 1; }
            else          { teach = tf_mask[step - 1]; ts = step - 1; }
            if (teach){ W = g_Wdec;   bias = g_bdec;  K = KCAT; }
            else      { W = g_Wsum16; bias = g_b2dec; K = KHn;  }
        }
        const int nst = K >> 7;                 // 9 (KCAT) or 8 (KHn)
        const int xfirst = (K == KCAT);
        const __half* hHp = g_hH[pin];

        auto kof = [&](int s){ return xfirst ? ((s == 0) ? KHn : (s - 1) << 7) : (s << 7); };

        wmma::fragment<wmma::accumulator,16,16,16,float> acc[2];
        wmma::fill_fragment(acc[0], 0.0f);
        wmma::fill_fragment(acc[1], 0.0f);

        auto issueA = [&](int s){
            const int k0 = kof(s);
            const uint32_t sb = ring_base + (uint32_t)(s & 3)*STAGE_BYTES;
            #pragma unroll
            for (int i = 0; i < 4; i++){
                int c = tid + (i << 8);                // 0..1023
                int r = c >> 4, q = c & 15;
                int k = k0 + (q << 3);
                const __half* p;
                if (k < KHn) p = hHp + (size_t)(mt*64 + r)*KHn + k;
                else         p = g_xH + ((size_t)ts*Bn + mt*64 + r)*In + (k - KHn);
                cp16(sb + (uint32_t)((OFF_Ah + r*PITCH + (q << 3))*2), p);
            }
        };
        auto issueW = [&](int s){
            const int k0 = kof(s);
            const uint32_t sb = ring_base + (uint32_t)(s & 3)*STAGE_BYTES;
            #pragma unroll
            for (int i = 0; i < 4; i++){
                int c = tid + (i << 8);
                int r = c >> 4, q = c & 15;
                cp16(sb + (uint32_t)((OFF_Bh + r*PITCH + (q << 3))*2),
                     W + (size_t)(nt*64 + r)*K + k0 + (q << 3));
            }
        };

        // close the cross-barrier prefetch group (W0-2 [+A0 if xfirst]) and
        // issue the remaining h-dependent A stages of the fill window.
        if (!xfirst) issueA(0);
        asm volatile("cp.async.commit_group;\n");      // G0: stage 0 complete set
        issueA(1); asm volatile("cp.async.commit_group;\n");
        issueA(2); asm volatile("cp.async.commit_group;\n");

        for (int s = 0; s < nst; s++){
            const int rem = nst - 1 - s;
            if (rem >= 2)      asm volatile("cp.async.wait_group 2;\n");
            else if (rem == 1) asm volatile("cp.async.wait_group 1;\n");
            else               asm volatile("cp.async.wait_group 0;\n");
            __syncthreads();   // stage s visible; all warps done with slot (s-1)&3
            if (s + 3 < nst){
                issueA(s + 3); issueW(s + 3);
                asm volatile("cp.async.commit_group;\n");
            }
            const __half* SB = RINGh + (size_t)(s & 3)*(STAGE_BYTES/2);
            #pragma unroll
            for (int kcl = 0; kcl < 8; kcl++){
                wmma::fragment<wmma::matrix_a,16,16,16,__half,wmma::row_major> aH;
                wmma::fragment<wmma::matrix_b,16,16,16,__half,wmma::col_major> b0, b1;
                wmma::load_matrix_sync(aH, SB + OFF_Ah + (wm*16)*PITCH + kcl*16, PITCH);
                wmma::load_matrix_sync(b0, SB + OFF_Bh + (wn*32)*PITCH + kcl*16, PITCH);
                wmma::load_matrix_sync(b1, SB + OFF_Bh + (wn*32 + 16)*PITCH + kcl*16, PITCH);
                wmma::mma_sync(acc[0], aH, b0, acc[0]);
                wmma::mma_sync(acc[1], aH, b1, acc[1]);
            }
        }

        // ---- D -> smem slot 3 (extra sync only if last stage used slot 3) ----
        if (nst == 8) __syncthreads();
        wmma::store_matrix_sync(&Dsm[(wm*16)*68 + wn*32 +  0], acc[0], 68, wmma::mem_row_major);
        wmma::store_matrix_sync(&Dsm[(wm*16)*68 + wn*32 + 16], acc[1], 68, wmma::mem_row_major);
        __syncthreads();

        // ---- epilogue phase A: compute cell, write ONLY cross-CTA state ----
        const bool valid = mode ? true : (step < lengths[m]);
        const float4 bi4 = *(const float4*)&bias[ubase];
        const float4 bf4 = *(const float4*)&bias[Hn + ubase];
        const float4 bg4 = *(const float4*)&bias[2*Hn + ubase];
        const float4 bo4 = *(const float4*)&bias[3*Hn + ubase];
        const float cold[4] = {cold4.x, cold4.y, cold4.z, cold4.w};
        const float bi[4] = {bi4.x, bi4.y, bi4.z, bi4.w};
        const float bf[4] = {bf4.x, bf4.y, bf4.z, bf4.w};
        const float bg[4] = {bg4.x, bg4.y, bg4.z, bg4.w};
        const float bo[4] = {bo4.x, bo4.y, bo4.z, bo4.w};
        float h2v[4], c2v[4];
        #pragma unroll
        for (int j = 0; j < 4; j++){
            float4 gv = *(const float4*)&Dsm[ml*68 + (tid & 3)*16 + j*4]; // i,f,g,o
            float iv = sigf(gv.x + bi[j]);
            float fv = sigf(gv.y + bf[j]);
            float gg = tanhf(gv.z + bg[j]);
            float ov = sigf(gv.w + bo[j]);
            c2v[j] = fmaf(fv, cold[j], iv*gg);
            h2v[j] = ov * tanhf(c2v[j]);
        }
        uint2 hpack;
        {
            __half2* hp = (__half2*)&hpack;
            hp[0] = make_half2(__float2half(h2v[0]), __float2half(h2v[1]));
            hp[1] = make_half2(__float2half(h2v[2]), __float2half(h2v[3]));
        }
        if (!mode && !valid) hpack = *(const uint2*)&g_hH[pin][idx0]; // bit-identical carry
        *(uint2*)&g_hH[pout][idx0] = hpack;
        __syncthreads();                       // all h writes issued
        if (tid == 0){
            __threadfence();                   // release
            atomicAdd((unsigned*)ctr, 1u);
        }

        // ---- phase B (overlaps barrier poll): local writes + next prefetch ----
        if (!mode){
            *(float4*)&g_c[idx0] = valid ? make_float4(c2v[0], c2v[1], c2v[2], c2v[3]) : cold4;
            *(float4*)&enc_out[((size_t)m*Tn + step)*Hn + ubase] =
                valid ? make_float4(h2v[0], h2v[1], h2v[2], h2v[3])
                      : make_float4(0.f, 0.f, 0.f, 0.f);
        } else {
            *(float4*)&g_c[idx0] = make_float4(c2v[0], c2v[1], c2v[2], c2v[3]);
            *(uint2*)&g_dech16[((size_t)step*Bn + m)*Hn + ubase] = hpack;
        }
        if (it + 1 < 2*Tn){                    // next-step W (+x) prefetch, uncommitted
            const __half* Wn; int Kn, tsn = 0;
            const int nit = it + 1;
            if (nit < Tn){ Wn = g_Wenc; Kn = KCAT; tsn = nit; }
            else {
                int nstep = nit - Tn;
                int teach = (nstep == 0) ? 1 : tf_mask[nstep - 1];
                if (teach){ Wn = g_Wdec; Kn = KCAT; tsn = (nstep == 0) ? Tn - 1 : nstep - 1; }
                else      { Wn = g_Wsum16; Kn = KHn; }
            }
            const int xf = (Kn == KCAT);
            #pragma unroll
            for (int s = 0; s < 3; s++){
                const int k0 = xf ? ((s == 0) ? KHn : (s - 1) << 7) : (s << 7);
                const uint32_t sb = ring_base + (uint32_t)s*STAGE_BYTES;
                #pragma unroll
                for (int i = 0; i < 4; i++){
                    int c = tid + (i << 8);
                    int r = c >> 4, q = c & 15;
                    cp16(sb + (uint32_t)((OFF_Bh + r*PITCH + (q << 3))*2),
                         Wn + (size_t)(nt*64 + r)*Kn + k0 + (q << 3));
                }
            }
            if (xf){                           // A stage 0 = x columns, h-independent
                #pragma unroll
                for (int i = 0; i < 4; i++){
                    int c = tid + (i << 8);
                    int r = c >> 4, q = c & 15;
                    cp16(ring_base + (uint32_t)((OFF_Ah + r*PITCH + (q << 3))*2),
                         g_xH + ((size_t)tsn*Bn + mt*64 + r)*In + (q << 3));
                }
            }
        }
        if (tid == 0){
            const unsigned goal = (unsigned)(it + 1) * 64u;
            while (*ctr < goal) {}
        }
        __syncthreads();                       // release all threads
    }
}

// ---------------------------------------------------------------------------
// Final output projection (fp16 wmma): out[b][s][:] = dech16[s][b][:]@linw16^T + b
// Grid (1024, 2): 64-row x 64-col tiles; same BK=128 ring pipeline.
// ---------------------------------------------------------------------------
__global__ __launch_bounds__(256, 1) void final_gemm16_kernel(
    const float* __restrict__ linb, float* __restrict__ out){
    extern __shared__ __align__(16) char DS[];
    __half* RINGh = (__half*)DS;
    float*  Dsm   = (float*)(DS + 3*STAGE_BYTES);    // alias of slot 3
    const uint32_t ring_base = (uint32_t)__cvta_generic_to_shared(DS);
    const int tid = threadIdx.x, wid = tid >> 5;
    const int wm = wid & 3, wn = wid >> 2;
    const int r0 = blockIdx.x << 6;                  // row tile (0..1023)
    const int n0 = blockIdx.y << 6;                  // col tile (0..1)

    auto issue = [&](int s){
        const int k0 = s << 7;
        const uint32_t sb = ring_base + (uint32_t)(s & 3)*STAGE_BYTES;
        #pragma unroll
        for (int i = 0; i < 4; i++){                 // A: 64 rows x 16 chunks
            int c = tid + (i << 8);
            int r = c >> 4, q = c & 15;
            cp16(sb + (uint32_t)((OFF_Ah + r*PITCH + (q << 3))*2),
                 g_dech16 + (size_t)(r0 + r)*Hn + k0 + (q << 3));
        }
        #pragma unroll
        for (int i = 0; i < 4; i++){                 // B: 64 rows x 16 chunks
            int c = tid + (i << 8);
            int r = c >> 4, q = c & 15;
            cp16(sb + (uint32_t)((OFF_Bh + r*PITCH + (q << 3))*2),
                 g_linw16 + (size_t)(n0 + r)*Hn + k0 + (q << 3));
        }
        asm volatile("cp.async.commit_group;\n");
    };

    wmma::fragment<wmma::accumulator,16,16,16,float> acc[2];
    wmma::fill_fragment(acc[0], 0.0f);
    wmma::fill_fragment(acc[1], 0.0f);

    issue(0); issue(1); issue(2);
    for (int s = 0; s < 8; s++){
        const int rem = 7 - s;
        if (rem >= 2)      asm volatile("cp.async.wait_group 2;\n");
        else if (rem == 1) asm volatile("cp.async.wait_group 1;\n");
        else               asm volatile("cp.async.wait_group 0;\n");
        __syncthreads();
        if (s + 3 < 8) issue(s + 3);
        const __half* SB = RINGh + (size_t)(s & 3)*(STAGE_BYTES/2);
        #pragma unroll
        for (int kcl = 0; kcl < 8; kcl++){
            wmma::fragment<wmma::matrix_a,16,16,16,__half,wmma::row_major> aH;
            wmma::fragment<wmma::matrix_b,16,16,16,__half,wmma::col_major> b0, b1;
            wmma::load_matrix_sync(aH, SB + OFF_Ah + (wm*16)*PITCH + kcl*16, PITCH);
            wmma::load_matrix_sync(b0, SB + OFF_Bh + (wn*32)*PITCH + kcl*16, PITCH);
            wmma::load_matrix_sync(b1, SB + OFF_Bh + (wn*32 + 16)*PITCH + kcl*16, PITCH);
            wmma::mma_sync(acc[0], aH, b0, acc[0]);
            wmma::mma_sync(acc[1], aH, b1, acc[1]);
        }
        __syncthreads();                       // reads done before slot reuse/D store
    }

    wmma::store_matrix_sync(&Dsm[(wm*16)*68 + wn*32 +  0], acc[0], 68, wmma::mem_row_major);
    wmma::store_matrix_sync(&Dsm[(wm*16)*68 + wn*32 + 16], acc[1], 68, wmma::mem_row_major);
    __syncthreads();

    const int ml = tid >> 2;
    const int r  = r0 + ml;
    const int s  = r >> 7;                     // time step
    const int b  = r & 127;                    // batch
    #pragma unroll
    for (int j = 0; j < 4; j++){
        const int c = (tid & 3)*16 + j*4;
        float4 v = *(const float4*)&Dsm[ml*68 + c];
        float4 lb = *(const float4*)&linb[n0 + c];
        v.x += lb.x; v.y += lb.y; v.z += lb.z; v.w += lb.w;
        *(float4*)&out[((size_t)b*Tn + s)*In + n0 + c] = v;
    }
}

// ---------------------------------------------------------------------------
// kernel_launch — 9 graph nodes. No __device__ symbol passed from host.
// Inputs: x_input, enc_Wih, enc_Whh, enc_bih, enc_bhh, dec_Wih, dec_Whh,
//         dec_bih, dec_bhh, lin_W, lin_b, lengths, tf_mask.
// Output: [outputs (B*T*I) | encoder_output (B*T*H)] float32.
// ---------------------------------------------------------------------------
extern "C" void kernel_launch(void* const* d_in, const int* in_sizes, int n_in,
                              void* d_out, int out_size){
    const float* x       = (const float*)d_in[0];
    const float* eWih    = (const float*)d_in[1];
    const float* eWhh    = (const float*)d_in[2];
    const float* ebih    = (const float*)d_in[3];
    const float* ebhh    = (const float*)d_in[4];
    const float* dWih    = (const float*)d_in[5];
    const float* dWhh    = (const float*)d_in[6];
    const float* dbih    = (const float*)d_in[7];
    const float* dbhh    = (const float*)d_in[8];
    const float* linW    = (const float*)d_in[9];
    const float* linb    = (const float*)d_in[10];
    const int*   lengths = (const int*)d_in[11];
    const int*   tfm     = (const int*)d_in[12];
    float* out = (float*)d_out;
    float* enc_out = out + (size_t)Bn*Tn*In;

    cudaFuncSetAttribute(lstm_persist_kernel,
                         cudaFuncAttributeMaxDynamicSharedMemorySize, SMEM_BYTES);
    cudaFuncSetAttribute(final_gemm16_kernel,
                         cudaFuncAttributeMaxDynamicSharedMemorySize, SMEM_BYTES);

    zero_state_kernel<<<(BHn + 255)/256, 256>>>();
    pack_w_kernel<<<(int)(((size_t)Gn*KCAT + 255)/256), 256>>>(eWhh, eWih, 0);
    pack_w_kernel<<<(int)(((size_t)Gn*KCAT + 255)/256), 256>>>(dWhh, dWih, 1);
    build_wsum_kernel<<<Gn, 256>>>(dWhh, dWih, linW);
    build_bias_kernel<<<(Gn + 255)/256, 256>>>(ebih, ebhh, dbih, dbhh, dWih, linb);
    pack_x_kernel<<<(int)(((size_t)Tn*Bn*In + 255)/256), 256>>>(x);
    pack_linw_kernel<<<(In*Hn + 255)/256, 256>>>(linW);

    lstm_persist_kernel<<<128, 256, SMEM_BYTES>>>(lengths, tfm, enc_out);

    final_gemm16_kernel<<<dim3((Tn*Bn)/64, In/64), 256, SMEM_BYTES>>>(linb, out);
}